// round 3
// baseline (speedup 1.0000x reference)
#include <cuda_runtime.h>
#include <cstdint>

// ---------------------------------------------------------------------------
// Problem constants
// ---------------------------------------------------------------------------
constexpr int Bk   = 256;   // batch
constexpr int Tk   = 128;   // seq len
constexpr int Vk   = 42;    // vocab
constexpr int LATk = 200;   // latent
constexpr int Uk   = 512;   // lstm units
constexpr int Pk   = 3;     // num_prop
constexpr int BT   = Bk * Tk;          // 32768
constexpr int G4U  = 4 * Uk;           // 2048
constexpr int DENC = LATk + Pk;        // 203
constexpr int DDEC = 2 * LATk + Pk;    // 403
constexpr int BU   = Bk * Uk;          // 131072

// ---------------------------------------------------------------------------
// Scratch layout in one big __device__ buffer (no allocations allowed)
// ---------------------------------------------------------------------------
constexpr size_t SZ_ENC_IN  = (size_t)BT * DENC;
constexpr size_t SZ_DEC_IN  = (size_t)BT * DDEC;
constexpr size_t SZ_PRE     = (size_t)BT * G4U;
constexpr size_t SZ_H       = (size_t)3 * 2 * BU;   // [layer][parity]
constexpr size_t SZ_C       = (size_t)3 * BU;
constexpr size_t SZ_DECOUT  = (size_t)BT * Uk;
constexpr size_t SZ_Z       = (size_t)Bk * LATk;
constexpr size_t SZ_LOGITS  = (size_t)BT * 64;
constexpr size_t SZ_WOPAD   = (size_t)Uk * 64;
constexpr size_t SZ_LATPART = 256;
constexpr size_t SZ_CEPART  = 128;

constexpr size_t OFF_ENC_IN  = 0;
constexpr size_t OFF_DEC_IN  = OFF_ENC_IN + SZ_ENC_IN;
constexpr size_t OFF_ENC_PRE = OFF_DEC_IN + SZ_DEC_IN;
constexpr size_t OFF_DEC_PRE = OFF_ENC_PRE + SZ_PRE;
constexpr size_t OFF_H       = OFF_DEC_PRE + SZ_PRE;
constexpr size_t OFF_C       = OFF_H + SZ_H;
constexpr size_t OFF_DECOUT  = OFF_C + SZ_C;
constexpr size_t OFF_Z       = OFF_DECOUT + SZ_DECOUT;
constexpr size_t OFF_LOGITS  = OFF_Z + SZ_Z;
constexpr size_t OFF_WOPAD   = OFF_LOGITS + SZ_LOGITS;
constexpr size_t OFF_LATPART = OFF_WOPAD + SZ_WOPAD;
constexpr size_t OFF_CEPART  = OFF_LATPART + SZ_LATPART;
constexpr size_t TOTAL_FLOATS = OFF_CEPART + SZ_CEPART;

__device__ __align__(128) float g_buf[TOTAL_FLOATS];

// ---------------------------------------------------------------------------
// Software grid barrier (sense reversal, self-resetting count).
// All NB blocks must be co-resident: NB=128 <= 148 SMs, 256thr/20.6KB smem.
// ---------------------------------------------------------------------------
constexpr int NB = 128;
__device__ unsigned g_count = 0;
__device__ volatile unsigned g_sense_v = 0;

__device__ __forceinline__ void gbar(unsigned& s)
{
    __syncthreads();
    if (threadIdx.x == 0) {
        __threadfence();
        if (atomicAdd(&g_count, 1u) == (unsigned)NB - 1u) {
            g_count = 0;
            __threadfence();
            g_sense_v = s ^ 1u;
        } else {
            while (g_sense_v == s) { __nanosleep(64); }
            __threadfence();
        }
    }
    __syncthreads();
    s ^= 1u;
}

__device__ __forceinline__ float sigm(float x) { return 1.f / (1.f + expf(-x)); }

// ---------------------------------------------------------------------------
// Persistent stacked-LSTM pass. One launch runs all 128 timesteps x 3 layers.
// Block (of 128) owns tile: rows m0..m0+31 (batch), units u0..u0+31.
// Per layer-step it computes its 32x(4*32) slice of z = [A1;A2]@[W1;W2],
// applies gates in-block, writes h/c, then grid-barriers.
// ---------------------------------------------------------------------------
__global__ __launch_bounds__(256) void lstm_pass_kernel(
    const float* __restrict__ pre,                      // [B*T, 2048], row b*T+t
    const float* __restrict__ rk0, const float* __restrict__ b0,
    const float* __restrict__ k1,  const float* __restrict__ rk1, const float* __restrict__ b1,
    const float* __restrict__ k2,  const float* __restrict__ rk2, const float* __restrict__ b2,
    float* __restrict__ h,                              // [3][2][BU]
    float* __restrict__ c,                              // [3][BU]
    float* __restrict__ dout)                           // null or [BT*Uk], row b*T+t
{
    __shared__ float As[32][33];     // [row][kk]
    __shared__ float Ws[32][128];    // [kk][gate*32 + ul]

    const int tid = threadIdx.x;
    const int blk = blockIdx.x;
    const int m0  = (blk >> 4) * 32;       // 8 m-tiles
    const int u0  = (blk & 15) * 32;       // 16 u-tiles
    const int rg  = tid >> 5;              // warp id = row group (0..7)
    const int ul  = tid & 31;              // lane  = unit within tile
    const int row0 = m0 + rg * 4;

    __shared__ unsigned ssense;
    if (tid == 0) ssense = g_sense_v;
    __syncthreads();
    unsigned sense = ssense;

    // Zero my h (both parities) and c tiles (fresh state each launch/replay).
    for (int l = 0; l < 3; l++) {
        for (int i = tid; i < 32 * 32; i += 256) {
            const int r = i >> 5, uu = i & 31;
            const size_t off = (size_t)(m0 + r) * Uk + u0 + uu;
            h[((size_t)l * 2 + 0) * BU + off] = 0.f;
            h[((size_t)l * 2 + 1) * BU + off] = 0.f;
            c[(size_t)l * BU + off] = 0.f;
        }
    }
    gbar(sense);

    for (int t = 0; t < Tk; t++) {
        const int p = t & 1, q = p ^ 1;
        for (int l = 0; l < 3; l++) {
            const float *A0, *W0, *A1s = nullptr, *W1s = nullptr, *bias;
            int nsrc;
            if (l == 0) {
                A0 = h + ((size_t)0 * 2 + q) * BU; W0 = rk0; bias = b0; nsrc = 1;
            } else if (l == 1) {
                A0 = h + ((size_t)0 * 2 + p) * BU; W0 = k1;
                A1s = h + ((size_t)1 * 2 + q) * BU; W1s = rk1; bias = b1; nsrc = 2;
            } else {
                A0 = h + ((size_t)1 * 2 + p) * BU; W0 = k2;
                A1s = h + ((size_t)2 * 2 + q) * BU; W1s = rk2; bias = b2; nsrc = 2;
            }

            float acc[4][4];
#pragma unroll
            for (int i = 0; i < 4; i++)
#pragma unroll
                for (int j = 0; j < 4; j++) acc[i][j] = 0.f;

            for (int src = 0; src < nsrc; src++) {
                const float* A = src ? A1s : A0;
                const float* W = src ? W1s : W0;
                for (int k0i = 0; k0i < Uk; k0i += 32) {
                    // load A tile: 1024 elems, 4/thread, coalesced over kk
                    {
                        int i = tid;
#pragma unroll
                        for (int it = 0; it < 4; it++) {
                            const int r = i >> 5, kk = i & 31;
                            As[r][kk] = A[(size_t)(m0 + r) * Uk + k0i + kk];
                            i += 256;
                        }
                    }
                    // load W tile: 32kk x 128cols, 16/thread
                    {
#pragma unroll
                        for (int it = 0; it < 16; it++) {
                            const int i = tid + it * 256;
                            const int kk = i >> 7, cc = i & 127;
                            const int g = cc >> 5, uu = cc & 31;
                            Ws[kk][cc] = W[(size_t)(k0i + kk) * G4U + g * Uk + u0 + uu];
                        }
                    }
                    __syncthreads();
#pragma unroll
                    for (int kk = 0; kk < 32; kk++) {
                        float a0 = As[rg * 4 + 0][kk];
                        float a1 = As[rg * 4 + 1][kk];
                        float a2 = As[rg * 4 + 2][kk];
                        float a3 = As[rg * 4 + 3][kk];
#pragma unroll
                        for (int g = 0; g < 4; g++) {
                            const float w = Ws[kk][g * 32 + ul];
                            acc[0][g] += a0 * w;
                            acc[1][g] += a1 * w;
                            acc[2][g] += a2 * w;
                            acc[3][g] += a3 * w;
                        }
                    }
                    __syncthreads();
                }
            }

            // gates (Keras order i,f,g,o)
            const int u = u0 + ul;
            const float bi = bias[0 * Uk + u];
            const float bf = bias[1 * Uk + u];
            const float bgg = bias[2 * Uk + u];
            const float bo_ = bias[3 * Uk + u];
#pragma unroll
            for (int ri = 0; ri < 4; ri++) {
                const int b = row0 + ri;
                float zi = acc[ri][0] + bi;
                float zf = acc[ri][1] + bf;
                float zg = acc[ri][2] + bgg;
                float zo = acc[ri][3] + bo_;
                if (l == 0) {
                    const size_t prow = ((size_t)b * Tk + t) * G4U;
                    zi += pre[prow + u];
                    zf += pre[prow + Uk + u];
                    zg += pre[prow + 2 * Uk + u];
                    zo += pre[prow + 3 * Uk + u];
                }
                const size_t ci = (size_t)l * BU + (size_t)b * Uk + u;
                const float ig = sigm(zi);
                const float fg = sigm(zf);
                const float gg = tanhf(zg);
                const float og = sigm(zo);
                const float cn = fg * c[ci] + ig * gg;
                c[ci] = cn;
                const float hn = og * tanhf(cn);
                h[((size_t)l * 2 + p) * BU + (size_t)b * Uk + u] = hn;
                if (l == 2 && dout) dout[((size_t)b * Tk + t) * Uk + u] = hn;
            }
            gbar(sense);
        }
    }
}

// ---------------------------------------------------------------------------
// Generic dual-source GEMM (single K chunk now): C = [A1|A2] @ [W1;W2]
// Tiles 64x64x32, 128 threads, 8m x 4n per thread.
// ---------------------------------------------------------------------------
__global__ __launch_bounds__(128) void gemm_dual(
    const float* __restrict__ A1, int D1,
    const float* __restrict__ A2, int D2,
    const float* __restrict__ W1, const float* __restrict__ W2,
    float* __restrict__ C, int M, int N)
{
    __shared__ float As[64][36];
    __shared__ __align__(16) float Ws[32][64];

    const int n0 = blockIdx.x * 64;
    const int m0 = blockIdx.y * 64;
    const int Ktot = D1 + D2;

    const int tid = threadIdx.x;
    const int tn0 = (tid & 15) * 4;
    const int tm0 = (tid >> 4) * 8;

    float acc[8][4];
#pragma unroll
    for (int i = 0; i < 8; i++)
#pragma unroll
        for (int j = 0; j < 4; j++) acc[i][j] = 0.f;

    const int a_kk = tid & 31;
    const int a_rg = (tid >> 5) * 16;
    const int w_n  = tid & 63;
    const int w_kg = tid >> 6;

    for (int k0 = 0; k0 < Ktot; k0 += 32) {
        {
            const int gk = k0 + a_kk;
            const bool valid = gk < Ktot;
            const bool in1 = gk < D1;
#pragma unroll
            for (int i = 0; i < 16; i++) {
                const int r = a_rg + i;
                float v = 0.f;
                if (valid) {
                    const int gm = m0 + r;
                    v = in1 ? A1[(size_t)gm * D1 + gk]
                            : A2[(size_t)gm * D2 + (gk - D1)];
                }
                As[r][a_kk] = v;
            }
        }
        {
#pragma unroll
            for (int i = 0; i < 16; i++) {
                const int kk = i * 2 + w_kg;
                const int gk = k0 + kk;
                float v = 0.f;
                if (gk < Ktot) {
                    v = (gk < D1) ? W1[(size_t)gk * N + n0 + w_n]
                                  : W2[(size_t)(gk - D1) * N + n0 + w_n];
                }
                Ws[kk][w_n] = v;
            }
        }
        __syncthreads();
#pragma unroll
        for (int kk = 0; kk < 32; kk++) {
            const float4 w = *reinterpret_cast<const float4*>(&Ws[kk][tn0]);
#pragma unroll
            for (int i = 0; i < 8; i++) {
                const float a = As[tm0 + i][kk];
                acc[i][0] += a * w.x;
                acc[i][1] += a * w.y;
                acc[i][2] += a * w.z;
                acc[i][3] += a * w.w;
            }
        }
        __syncthreads();
    }

#pragma unroll
    for (int i = 0; i < 8; i++) {
        float4 v = make_float4(acc[i][0], acc[i][1], acc[i][2], acc[i][3]);
        *reinterpret_cast<float4*>(&C[(size_t)(m0 + tm0 + i) * N + n0 + tn0]) = v;
    }
}

// ---------------------------------------------------------------------------
// Input builders
// ---------------------------------------------------------------------------
__global__ void build_enc_in(const int* __restrict__ X, const float* __restrict__ C,
                             const float* __restrict__ emb, float* __restrict__ out)
{
    const size_t idx = (size_t)blockIdx.x * 256 + threadIdx.x;
    if (idx >= (size_t)BT * DENC) return;
    const int col = (int)(idx % DENC);
    const int bt  = (int)(idx / DENC);
    const int b   = bt >> 7;
    float v;
    if (col < LATk) {
        int x = X[bt]; x = min(max(x, 0), Vk - 1);
        v = emb[x * LATk + col];
    } else {
        v = C[b * Pk + (col - LATk)];
    }
    out[idx] = v;
}

__global__ void build_dec_in(const int* __restrict__ X, const float* __restrict__ C,
                             const float* __restrict__ emb, const float* __restrict__ z,
                             float* __restrict__ out)
{
    const size_t idx = (size_t)blockIdx.x * 256 + threadIdx.x;
    if (idx >= (size_t)BT * DDEC) return;
    const int col = (int)(idx % DDEC);
    const int bt  = (int)(idx / DDEC);
    const int b   = bt >> 7;
    float v;
    if (col < LATk) {
        v = z[b * LATk + col];
    } else if (col < 2 * LATk) {
        int x = X[bt]; x = min(max(x, 0), Vk - 1);
        v = emb[x * LATk + (col - LATk)];
    } else {
        v = C[b * Pk + (col - 2 * LATk)];
    }
    out[idx] = v;
}

// ---------------------------------------------------------------------------
// Latent head: z = mean + exp(ls/2)*eps ; per-batch KL partials
// ---------------------------------------------------------------------------
__global__ __launch_bounds__(256) void latent_kernel(
    const float* __restrict__ hc, const float* __restrict__ Wm, const float* __restrict__ bm,
    const float* __restrict__ Wsw, const float* __restrict__ bsw,
    const float* __restrict__ eps, float* __restrict__ z, float* __restrict__ latpart)
{
    const int b = blockIdx.x;
    __shared__ float hs[Uk];
    __shared__ float red[256];
    const int tid = threadIdx.x;
    hs[tid]       = hc[b * Uk + tid];
    hs[tid + 256] = hc[b * Uk + 256 + tid];
    __syncthreads();

    float part = 0.f;
    if (tid < LATk) {
        float m = bm[tid], s = bsw[tid];
        for (int k = 0; k < Uk; k++) {
            const float hv = hs[k];
            m += hv * Wm[k * LATk + tid];
            s += hv * Wsw[k * LATk + tid];
        }
        z[b * LATk + tid] = m + expf(0.5f * s) * eps[b * LATk + tid];
        part = 1.f + s - m * m - expf(s);
    }
    red[tid] = part;
    __syncthreads();
    for (int s2 = 128; s2 > 0; s2 >>= 1) {
        if (tid < s2) red[tid] += red[tid + s2];
        __syncthreads();
    }
    if (tid == 0) latpart[b] = red[0];
}

__global__ void pad_wo(const float* __restrict__ Wo, float* __restrict__ Wp)
{
    const int idx = blockIdx.x * 256 + threadIdx.x;
    if (idx >= Uk * 64) return;
    const int k = idx >> 6, ccol = idx & 63;
    Wp[idx] = (ccol < Vk) ? Wo[k * Vk + ccol] : 0.f;
}

__global__ __launch_bounds__(256) void ce_kernel(
    const float* __restrict__ logits, const float* __restrict__ bo,
    const int* __restrict__ Y, const int* __restrict__ L,
    float* __restrict__ cepart)
{
    const int row = blockIdx.x * 256 + threadIdx.x;
    const float* lr = logits + (size_t)row * 64;
    float mx = -1e30f;
#pragma unroll
    for (int j = 0; j < Vk; j++) mx = fmaxf(mx, lr[j] + bo[j]);
    float se = 0.f;
#pragma unroll
    for (int j = 0; j < Vk; j++) se += expf(lr[j] + bo[j] - mx);
    int y = Y[row]; y = min(max(y, 0), Vk - 1);
    const float lp = (lr[y] + bo[y]) - mx - logf(se);
    const int b = row >> 7, t = row & 127;
    const float w = (t < L[b]) ? 1.f : 0.f;
    const float val = -lp * w;

    __shared__ float red[256];
    red[threadIdx.x] = val;
    __syncthreads();
    for (int s = 128; s > 0; s >>= 1) {
        if (threadIdx.x < s) red[threadIdx.x] += red[threadIdx.x + s];
        __syncthreads();
    }
    if (threadIdx.x == 0) cepart[blockIdx.x] = red[0];
}

__global__ void final_kernel(const float* __restrict__ cepart,
                             const float* __restrict__ latpart,
                             float* __restrict__ out, int out_size)
{
    __shared__ float red[256];
    const int tid = threadIdx.x;
    red[tid] = latpart[tid];
    __syncthreads();
    for (int s = 128; s > 0; s >>= 1) {
        if (tid < s) red[tid] += red[tid + s];
        __syncthreads();
    }
    const float latsum = red[0];
    __syncthreads();
    red[tid] = (tid < 128) ? cepart[tid] : 0.f;
    __syncthreads();
    for (int s = 128; s > 0; s >>= 1) {
        if (tid < s) red[tid] += red[tid + s];
        __syncthreads();
    }
    if (tid == 0) {
        const float recon  = red[0] / (float)(Bk * Tk);
        const float latent = -0.5f * latsum / (float)(Bk * LATk);
        if (out_size >= 1) out[0] = recon + latent;
        if (out_size >= 2) out[1] = recon;
        if (out_size >= 3) out[2] = latent;
    }
}

// ---------------------------------------------------------------------------
// Host driver: 11 kernel nodes total (graph-upload stays in driver pools)
// ---------------------------------------------------------------------------
extern "C" void kernel_launch(void* const* d_in, const int* in_sizes, int n_in,
                              void* d_out, int out_size)
{
    const int*   X       = (const int*)d_in[0];
    const int*   Y       = (const int*)d_in[1];
    const float* Cc      = (const float*)d_in[2];
    const int*   L       = (const int*)d_in[3];
    const float* eps     = (const float*)d_in[4];
    const float* emb_enc = (const float*)d_in[5];
    const float* emb_dec = (const float*)d_in[6];
    const float* ek0  = (const float*)d_in[7];
    const float* erk0 = (const float*)d_in[8];
    const float* eb0  = (const float*)d_in[9];
    const float* ek1  = (const float*)d_in[10];
    const float* erk1 = (const float*)d_in[11];
    const float* eb1  = (const float*)d_in[12];
    const float* ek2  = (const float*)d_in[13];
    const float* erk2 = (const float*)d_in[14];
    const float* eb2  = (const float*)d_in[15];
    const float* dk0  = (const float*)d_in[16];
    const float* drk0 = (const float*)d_in[17];
    const float* db0  = (const float*)d_in[18];
    const float* dk1  = (const float*)d_in[19];
    const float* drk1 = (const float*)d_in[20];
    const float* db1  = (const float*)d_in[21];
    const float* dk2  = (const float*)d_in[22];
    const float* drk2 = (const float*)d_in[23];
    const float* db2  = (const float*)d_in[24];
    const float* Wm   = (const float*)d_in[25];
    const float* bm   = (const float*)d_in[26];
    const float* Wsw  = (const float*)d_in[27];
    const float* bsw  = (const float*)d_in[28];
    const float* Wo   = (const float*)d_in[29];
    const float* bo   = (const float*)d_in[30];

    float* base = nullptr;
    cudaGetSymbolAddress((void**)&base, g_buf);

    float* enc_in  = base + OFF_ENC_IN;
    float* dec_in  = base + OFF_DEC_IN;
    float* enc_pre = base + OFF_ENC_PRE;
    float* dec_pre = base + OFF_DEC_PRE;
    float* hbuf    = base + OFF_H;
    float* cbuf    = base + OFF_C;
    float* dec_out = base + OFF_DECOUT;
    float* zlat    = base + OFF_Z;
    float* logits  = base + OFF_LOGITS;
    float* wopad   = base + OFF_WOPAD;
    float* latpart = base + OFF_LATPART;
    float* cepart  = base + OFF_CEPART;

    pad_wo<<<(Uk * 64 + 255) / 256, 256>>>(Wo, wopad);

    // ---- encoder ----
    {
        size_t n = (size_t)BT * DENC;
        build_enc_in<<<(unsigned)((n + 255) / 256), 256>>>(X, Cc, emb_enc, enc_in);
    }
    gemm_dual<<<dim3(G4U / 64, BT / 64), 128>>>(enc_in, DENC, nullptr, 0,
                                                ek0, nullptr, enc_pre, BT, G4U);
    lstm_pass_kernel<<<NB, 256>>>(enc_pre, erk0, eb0, ek1, erk1, eb1, ek2, erk2, eb2,
                                  hbuf, cbuf, nullptr);

    // ---- latent (cell state of last encoder layer) ----
    latent_kernel<<<Bk, 256>>>(cbuf + (size_t)2 * BU, Wm, bm, Wsw, bsw, eps, zlat, latpart);

    // ---- decoder ----
    {
        size_t n = (size_t)BT * DDEC;
        build_dec_in<<<(unsigned)((n + 255) / 256), 256>>>(X, Cc, emb_dec, zlat, dec_in);
    }
    gemm_dual<<<dim3(G4U / 64, BT / 64), 128>>>(dec_in, DDEC, nullptr, 0,
                                                dk0, nullptr, dec_pre, BT, G4U);
    lstm_pass_kernel<<<NB, 256>>>(dec_pre, drk0, db0, dk1, drk1, db1, dk2, drk2, db2,
                                  hbuf, cbuf, dec_out);

    // ---- logits: dec_out @ Wo(padded) ----
    gemm_dual<<<dim3(1, BT / 64), 128>>>(dec_out, Uk, nullptr, 0,
                                         wopad, nullptr, logits, BT, 64);

    // ---- losses ----
    ce_kernel<<<BT / 256, 256>>>(logits, bo, Y, L, cepart);
    final_kernel<<<1, 256>>>(cepart, latpart, (float*)d_out, out_size);
}